// round 12
// baseline (speedup 1.0000x reference)
#include <cuda_runtime.h>
#include <stdint.h>

// Problem constants
#define BATCH 4096
#define FEAT  4096
#define NP    16
#define DDIM  256
#define MROWS (BATCH * NP)   // 65536
#define EPS   1e-5f
#define QPRE   0.09017131f   // (1/sqrt(256)) * log2(e)

// ---------------- device scratch ----------------
#define RCHUNKS 64
__device__ float g_psum[RCHUNKS * FEAT];
__device__ float g_psumsq[RCHUNKS * FEAT];
__device__ float g_scale[FEAT];
__device__ float g_shift[FEAT];
__device__ uint32_t g_xnh[(size_t)MROWS * 128];  // BN(x) fp16x2, 32 MB
__device__ uint32_t g_wh[3 * 256 * 128];          // weights fp16x2 (WQ pre-scaled)
__device__ uint32_t g_qh[(size_t)MROWS * 128];    // Q' fp16x2
__device__ uint32_t g_kh[(size_t)MROWS * 128];
__device__ uint32_t g_vh[(size_t)MROWS * 128];

__device__ __forceinline__ uint32_t hpack(float y0, float y1) {
    uint32_t h;
    asm("cvt.rn.f16x2.f32 %0, %1, %2;" : "=r"(h) : "f"(y1), "f"(y0));
    return h;
}
__device__ __forceinline__ float ex2(float x) {
    float r;
    asm("ex2.approx.f32 %0, %1;" : "=f"(r) : "f"(x));
    return r;
}
__device__ __forceinline__ void cp16(uint32_t daddr, const void* src) {
    asm volatile("cp.async.cg.shared.global [%0], [%1], 16;"
                 :: "r"(daddr), "l"(src) : "memory");
}

#define MMA_FP16(c, a0, a1, a2, a3, b0, b1)                                \
    asm volatile(                                                          \
        "mma.sync.aligned.m16n8k16.row.col.f32.f16.f16.f32 "               \
        "{%0,%1,%2,%3}, {%4,%5,%6,%7}, {%8,%9}, {%0,%1,%2,%3};"            \
        : "+f"((c)[0]), "+f"((c)[1]), "+f"((c)[2]), "+f"((c)[3])           \
        : "r"(a0), "r"(a1), "r"(a2), "r"(a3), "r"(b0), "r"(b1))

// ---------------- BN pass 1 ----------------
__global__ void bn_pass1(const float* __restrict__ x) {
    int col = blockIdx.x * 256 + threadIdx.x;
    int r0  = blockIdx.y * (BATCH / RCHUNKS);
    float s = 0.f, ss = 0.f;
    #pragma unroll 4
    for (int r = 0; r < BATCH / RCHUNKS; r++) {
        float v = x[(size_t)(r0 + r) * FEAT + col];
        s += v; ss += v * v;
    }
    g_psum[blockIdx.y * FEAT + col]   = s;
    g_psumsq[blockIdx.y * FEAT + col] = ss;
}

// ---------------- BN pass 2 ----------------
__global__ void bn_pass2(const float* __restrict__ gamma,
                         const float* __restrict__ beta) {
    int col = blockIdx.x * blockDim.x + threadIdx.x;
    float s = 0.f, ss = 0.f;
    #pragma unroll
    for (int c = 0; c < RCHUNKS; c++) {
        s  += g_psum[c * FEAT + col];
        ss += g_psumsq[c * FEAT + col];
    }
    float mean = s * (1.f / BATCH);
    float var  = ss * (1.f / BATCH) - mean * mean;
    float rstd = rsqrtf(var + EPS);
    float a = rstd * gamma[col];
    g_scale[col] = a;
    g_shift[col] = beta[col] - mean * a;
}

// ---------------- xn -> fp16 (BN fused), 16 elems/thread ----------------
__global__ void xn_fp16(const float* __restrict__ x) {
    int i = blockIdx.x * 256 + threadIdx.x;
    size_t e = (size_t)i * 16;
    int col = (int)(e & 4095);
    #pragma unroll
    for (int h = 0; h < 2; h++) {
        float4 v0 = *(const float4*)(x + e + h * 8);
        float4 v1 = *(const float4*)(x + e + h * 8 + 4);
        float4 sc0 = *(const float4*)(g_scale + col + h * 8);
        float4 sc1 = *(const float4*)(g_scale + col + h * 8 + 4);
        float4 sh0 = *(const float4*)(g_shift + col + h * 8);
        float4 sh1 = *(const float4*)(g_shift + col + h * 8 + 4);
        uint4 o;
        o.x = hpack(fmaf(v0.x, sc0.x, sh0.x), fmaf(v0.y, sc0.y, sh0.y));
        o.y = hpack(fmaf(v0.z, sc0.z, sh0.z), fmaf(v0.w, sc0.w, sh0.w));
        o.z = hpack(fmaf(v1.x, sc1.x, sh1.x), fmaf(v1.y, sc1.y, sh1.y));
        o.w = hpack(fmaf(v1.z, sc1.z, sh1.z), fmaf(v1.w, sc1.w, sh1.w));
        *(uint4*)(g_xnh + e / 2 + h * 4) = o;
    }
}

// ---------------- W -> fp16 (WQ scaled by QPRE) ----------------
__global__ void w_fp16(const float* __restrict__ wq,
                       const float* __restrict__ wk,
                       const float* __restrict__ wv) {
    int i = blockIdx.x * 256 + threadIdx.x;    // pair index, 3*32768 total
    int w = i >> 15;
    int idx = i & 32767;
    const float* src = (w == 0) ? wq : (w == 1) ? wk : wv;
    float2 v = ((const float2*)src)[idx];
    float s = (w == 0) ? QPRE : 1.f;
    g_wh[i] = hpack(v.x * s, v.y * s);
}

// ---------------- fp16 cp.async QKV GEMM, 512 threads ----------------
// grid (3, 512). 512 thr = 16 warps (4m x 4n), warp tile m32 x n64.
// BK=32 (8 chunks), 4-stage cp.async ring, ONE sync per chunk.
#define GP    20                          // uint32 pitch per row
#define A_STG (128 * GP)
#define B_STG (256 * GP)
#define NSTG  4
#define SMEM_GEMM ((A_STG + B_STG) * NSTG * 4)   // 122880 bytes

__global__ void __launch_bounds__(512, 1) gemm_mma(
    const float* __restrict__ bq, const float* __restrict__ bk_,
    const float* __restrict__ bv)
{
    extern __shared__ uint32_t smu[];
    const int tid = threadIdx.x;
    const int w   = blockIdx.x;
    const int m0  = blockIdx.y * 128;

    const float* bias = (w == 0) ? bq : (w == 1) ? bk_ : bv;
    uint32_t*    outp = (w == 0) ? g_qh : (w == 1) ? g_kh : g_vh;
    const float  bs   = (w == 0) ? QPRE : 1.f;

    const int lane = tid & 31, wid = tid >> 5;
    const int wm = wid >> 2, wn = wid & 3;     // 4 x 4 warps
    const int g4 = lane >> 2, l4 = lane & 3;

    const uint32_t* asrc = g_xnh + (size_t)m0 * 128;
    const uint32_t* bsrc = g_wh + w * 32768;
    uint32_t sbase = (uint32_t)__cvta_generic_to_shared(smu);

    auto ISSUE = [&](int c, int st) {
        {
            int row = tid >> 2, seg = tid & 3;
            cp16(sbase + (st * A_STG + row * GP + seg * 4) * 4,
                 asrc + (size_t)row * 128 + c * 16 + seg * 4);
        }
        #pragma unroll
        for (int t = 0; t < 2; t++) {
            int i = tid + t * 512;
            int row = i >> 2, seg = i & 3;
            cp16(sbase + (NSTG * A_STG + st * B_STG + row * GP + seg * 4) * 4,
                 bsrc + (size_t)row * 128 + c * 16 + seg * 4);
        }
        asm volatile("cp.async.commit_group;" ::: "memory");
    };

    float acc[2][8][4];
    #pragma unroll
    for (int tm = 0; tm < 2; tm++)
        #pragma unroll
        for (int nt = 0; nt < 8; nt++)
            #pragma unroll
            for (int i = 0; i < 4; i++) acc[tm][nt][i] = 0.f;

    ISSUE(0, 0); ISSUE(1, 1); ISSUE(2, 2);

    #pragma unroll 1
    for (int c = 0; c < 8; c++) {
        if (c < 6) {
            asm volatile("cp.async.wait_group 2;" ::: "memory");
        } else {
            asm volatile("cp.async.wait_group 0;" ::: "memory");
        }
        __syncthreads();
        // Safe to prefetch chunk c+3 now: it overwrites stage (c-1)&3, which
        // every warp finished reading before the barrier above.
        if (c < 5) ISSUE(c + 3, (c + 3) & 3);
        const int st = c & 3;
        const uint32_t* A0 = smu + st * A_STG + (wm * 32) * GP;
        const uint32_t* B0 = smu + NSTG * A_STG + st * B_STG + (wn * 64) * GP;
        #pragma unroll
        for (int kk = 0; kk < 2; kk++) {
            uint32_t af[2][4];
            #pragma unroll
            for (int tm = 0; tm < 2; tm++) {
                int r = tm * 16 + g4;
                af[tm][0] = A0[r * GP + kk * 8 + l4];
                af[tm][1] = A0[(r + 8) * GP + kk * 8 + l4];
                af[tm][2] = A0[r * GP + kk * 8 + l4 + 4];
                af[tm][3] = A0[(r + 8) * GP + kk * 8 + l4 + 4];
            }
            #pragma unroll
            for (int nt = 0; nt < 8; nt++) {
                uint32_t fb0 = B0[(nt * 8 + g4) * GP + kk * 8 + l4];
                uint32_t fb1 = B0[(nt * 8 + g4) * GP + kk * 8 + l4 + 4];
                #pragma unroll
                for (int tm = 0; tm < 2; tm++)
                    MMA_FP16(acc[tm][nt], af[tm][0], af[tm][1],
                             af[tm][2], af[tm][3], fb0, fb1);
            }
        }
    }

    // ---- epilogue: bias add (scaled), pack fp16, store ----
    const int rbase = m0 + wm * 32;
    const int cbase = wn * 64;
    #pragma unroll
    for (int tm = 0; tm < 2; tm++) {
        int r = rbase + tm * 16 + g4;
        #pragma unroll
        for (int nt = 0; nt < 8; nt++) {
            int col = cbase + nt * 8 + l4 * 2;
            float2 bb = *(const float2*)(bias + col);
            float bx = bb.x * bs, by = bb.y * bs;
            outp[(size_t)r * 128 + (col >> 1)] =
                hpack(acc[tm][nt][0] + bx, acc[tm][nt][1] + by);
            outp[(size_t)(r + 8) * 128 + (col >> 1)] =
                hpack(acc[tm][nt][2] + bx, acc[tm][nt][3] + by);
        }
    }
}

// ---------------- fp16 tensor-core attention, 128-thr CTA, 2/batch --------
#define APITCH 12
#define VPITCH 132
#define SMEM_ATTN ((128 + 256) * APITCH * 4 + 16 * VPITCH * 4)   // 26880 B

__global__ void __launch_bounds__(128) attn_tc(const float* __restrict__ x,
                                               float* __restrict__ out)
{
    extern __shared__ uint32_t smq[];
    uint32_t* Qt = smq;                    // [128 e][p-pair] fp16x2 (pre-scaled)
    uint32_t* Kt = smq + 128 * APITCH;     // [256 f][p-pair]
    uint32_t* Vh = smq + (128 + 256) * APITCH;   // [16 p][f-pair]

    const int b    = blockIdx.x;
    const int half = blockIdx.y;
    const int tid  = threadIdx.x;
    const int lane = tid & 31, wid = tid >> 5;
    const int g4 = lane >> 2, l4 = lane & 3;

    // ---- Q (this half) + K (full): load fp16 rows, transpose via prmt ----
    {
        const int j  = tid & 7;                 // p-pair
        const int e0 = (tid >> 3) * 8;          // local e base
        {
            const uint32_t* q0 = g_qh + ((size_t)b * 16 + 2 * j) * 128
                                 + half * 64 + (e0 >> 1);
            uint4 qa = *(const uint4*)q0;
            uint4 qb = *(const uint4*)(q0 + 128);
            uint32_t av4[4] = {qa.x, qa.y, qa.z, qa.w};
            uint32_t bv4[4] = {qb.x, qb.y, qb.z, qb.w};
            #pragma unroll
            for (int i = 0; i < 4; i++) {
                Qt[(e0 + 2 * i) * APITCH + j]     = __byte_perm(av4[i], bv4[i], 0x5410);
                Qt[(e0 + 2 * i + 1) * APITCH + j] = __byte_perm(av4[i], bv4[i], 0x7632);
            }
        }
        #pragma unroll
        for (int r = 0; r < 2; r++) {
            int f0 = r * 128 + e0;
            const uint32_t* k0 = g_kh + ((size_t)b * 16 + 2 * j) * 128 + (f0 >> 1);
            uint4 ka = *(const uint4*)k0;
            uint4 kb = *(const uint4*)(k0 + 128);
            uint32_t av4[4] = {ka.x, ka.y, ka.z, ka.w};
            uint32_t bv4[4] = {kb.x, kb.y, kb.z, kb.w};
            #pragma unroll
            for (int i = 0; i < 4; i++) {
                Kt[(f0 + 2 * i) * APITCH + j]     = __byte_perm(av4[i], bv4[i], 0x5410);
                Kt[(f0 + 2 * i + 1) * APITCH + j] = __byte_perm(av4[i], bv4[i], 0x7632);
            }
        }
    }
    // ---- V: direct fp16 copy [p][f-pair] ----
    {
        const int p  = tid >> 3;
        const int t8 = (tid & 7) * 16;
        const uint4* vsrc = (const uint4*)(g_vh + ((size_t)b * 16 + p) * 128 + t8);
        uint4* vdst = (uint4*)(Vh + p * VPITCH + t8);
        vdst[0] = vsrc[0];
        vdst[1] = vsrc[1];
        vdst[2] = vsrc[2];
        vdst[3] = vsrc[3];
    }
    __syncthreads();

    // ---- persistent Q fragments (already QPRE-scaled) ----
    uint32_t af[2][4];
    #pragma unroll
    for (int tm = 0; tm < 2; tm++) {
        int eb = wid * 32 + tm * 16;
        af[tm][0] = Qt[(eb + g4) * APITCH + l4];
        af[tm][1] = Qt[(eb + g4 + 8) * APITCH + l4];
        af[tm][2] = Qt[(eb + g4) * APITCH + l4 + 4];
        af[tm][3] = Qt[(eb + g4 + 8) * APITCH + l4 + 4];
    }

    float av[2][2][4];
    #pragma unroll
    for (int tm = 0; tm < 2; tm++)
        #pragma unroll
        for (int np = 0; np < 2; np++)
            #pragma unroll
            for (int i = 0; i < 4; i++) av[tm][np][i] = 0.f;
    float srow[2][2] = {{0.f, 0.f}, {0.f, 0.f}};

    #pragma unroll 2
    for (int fc = 0; fc < 256; fc += 32) {
        float E[2][4][4];
        // ---- S: 4 n-tiles x 2 m-tiles ----
        #pragma unroll
        for (int nt = 0; nt < 4; nt++) {
            int f = fc + nt * 8 + g4;
            uint32_t kb0 = Kt[f * APITCH + l4];
            uint32_t kb1 = Kt[f * APITCH + l4 + 4];
            #pragma unroll
            for (int tm = 0; tm < 2; tm++) {
                float* c = E[tm][nt];
                c[0] = c[1] = c[2] = c[3] = 0.f;
                MMA_FP16(c, af[tm][0], af[tm][1], af[tm][2], af[tm][3],
                         kb0, kb1);
            }
        }
        // ---- exp2 + row sums ----
        #pragma unroll
        for (int tm = 0; tm < 2; tm++)
            #pragma unroll
            for (int nt = 0; nt < 4; nt++) {
                float* c = E[tm][nt];
                c[0] = ex2(c[0]);
                c[1] = ex2(c[1]);
                c[2] = ex2(c[2]);
                c[3] = ex2(c[3]);
                srow[tm][0] += c[0] + c[1];
                srow[tm][1] += c[2] + c[3];
            }
        // ---- AV: P(fp16) x V(fp16) ----
        #pragma unroll
        for (int s = 0; s < 2; s++) {
            uint32_t vb0[2], vb1[2];
            #pragma unroll
            for (int np = 0; np < 2; np++) {
                const uint32_t* vr = Vh + (np * 8 + g4) * VPITCH + (fc >> 1) + s * 8;
                vb0[np] = vr[l4];
                vb1[np] = vr[l4 + 4];
            }
            #pragma unroll
            for (int tm = 0; tm < 2; tm++) {
                uint32_t a0 = hpack(E[tm][2 * s][0], E[tm][2 * s][1]);
                uint32_t a1 = hpack(E[tm][2 * s][2], E[tm][2 * s][3]);
                uint32_t a2 = hpack(E[tm][2 * s + 1][0], E[tm][2 * s + 1][1]);
                uint32_t a3 = hpack(E[tm][2 * s + 1][2], E[tm][2 * s + 1][3]);
                #pragma unroll
                for (int np = 0; np < 2; np++)
                    MMA_FP16(av[tm][np], a0, a1, a2, a3, vb0[np], vb1[np]);
            }
        }
    }

    // ---- epilogue ----
    #pragma unroll
    for (int tm = 0; tm < 2; tm++) {
        float s0 = srow[tm][0];
        s0 += __shfl_xor_sync(0xffffffffu, s0, 1);
        s0 += __shfl_xor_sync(0xffffffffu, s0, 2);
        float s1 = srow[tm][1];
        s1 += __shfl_xor_sync(0xffffffffu, s1, 1);
        s1 += __shfl_xor_sync(0xffffffffu, s1, 2);
        float inv0 = 1.f / s0, inv1 = 1.f / s1;
        int e_lo = half * 128 + wid * 32 + tm * 16 + g4;
        #pragma unroll
        for (int np = 0; np < 2; np++) {
            int p = np * 8 + l4 * 2;
            size_t lo = (size_t)b * FEAT + e_lo * 16 + p;
            size_t hi = lo + 8 * 16;
            float2 x0 = *(const float2*)(x + lo);
            float2 x1 = *(const float2*)(x + hi);
            *(float2*)(out + lo) = make_float2(av[tm][np][0] * inv0 + x0.x,
                                               av[tm][np][1] * inv0 + x0.y);
            *(float2*)(out + hi) = make_float2(av[tm][np][2] * inv1 + x1.x,
                                               av[tm][np][3] * inv1 + x1.y);
        }
    }
}

// ---------------- launcher ----------------
extern "C" void kernel_launch(void* const* d_in, const int* in_sizes, int n_in,
                              void* d_out, int out_size) {
    const float* x     = (const float*)d_in[0];
    const float* WQ_w  = (const float*)d_in[1];
    const float* WQ_b  = (const float*)d_in[2];
    const float* WK_w  = (const float*)d_in[3];
    const float* WK_b  = (const float*)d_in[4];
    const float* WV_w  = (const float*)d_in[5];
    const float* WV_b  = (const float*)d_in[6];
    const float* gamma = (const float*)d_in[7];
    const float* beta  = (const float*)d_in[8];
    float* out = (float*)d_out;

    cudaFuncSetAttribute(gemm_mma, cudaFuncAttributeMaxDynamicSharedMemorySize,
                         SMEM_GEMM);
    cudaFuncSetAttribute(attn_tc, cudaFuncAttributeMaxDynamicSharedMemorySize,
                         SMEM_ATTN);

    bn_pass1<<<dim3(FEAT / 256, RCHUNKS), 256>>>(x);
    w_fp16<<<384, 256>>>(WQ_w, WK_w, WV_w);
    bn_pass2<<<FEAT / 256, 256>>>(gamma, beta);
    xn_fp16<<<(MROWS * 256 / 16) / 256, 256>>>(x);
    gemm_mma<<<dim3(3, 512), 512, SMEM_GEMM>>>(WQ_b, WK_b, WV_b);
    attn_tc<<<dim3(BATCH, 2), 128, SMEM_ATTN>>>(x, out);
}

// round 13
// speedup vs baseline: 1.0366x; 1.0366x over previous
#include <cuda_runtime.h>
#include <stdint.h>

// Problem constants
#define BATCH 4096
#define FEAT  4096
#define NP    16
#define DDIM  256
#define MROWS (BATCH * NP)   // 65536
#define EPS   1e-5f
#define QPRE   0.09017131f   // (1/sqrt(256)) * log2(e)

// ---------------- device scratch ----------------
#define RCHUNKS 64
__device__ float g_psum[RCHUNKS * FEAT];
__device__ float g_psumsq[RCHUNKS * FEAT];
__device__ float g_scale[FEAT];
__device__ float g_shift[FEAT];
__device__ uint32_t g_xnh[(size_t)MROWS * 128];  // BN(x) fp16x2, 32 MB
__device__ uint32_t g_wh[3 * 256 * 128];          // weights fp16x2 (WQ pre-scaled)
__device__ uint32_t g_qh[(size_t)MROWS * 128];    // Q' fp16x2
__device__ uint32_t g_kh[(size_t)MROWS * 128];
__device__ uint32_t g_vh[(size_t)MROWS * 128];

__device__ __forceinline__ uint32_t hpack(float y0, float y1) {
    uint32_t h;
    asm("cvt.rn.f16x2.f32 %0, %1, %2;" : "=r"(h) : "f"(y1), "f"(y0));
    return h;
}
__device__ __forceinline__ float ex2(float x) {
    float r;
    asm("ex2.approx.f32 %0, %1;" : "=f"(r) : "f"(x));
    return r;
}
__device__ __forceinline__ void cp16(uint32_t daddr, const void* src) {
    asm volatile("cp.async.cg.shared.global [%0], [%1], 16;"
                 :: "r"(daddr), "l"(src) : "memory");
}

#define MMA_FP16(c, a0, a1, a2, a3, b0, b1)                                \
    asm volatile(                                                          \
        "mma.sync.aligned.m16n8k16.row.col.f32.f16.f16.f32 "               \
        "{%0,%1,%2,%3}, {%4,%5,%6,%7}, {%8,%9}, {%0,%1,%2,%3};"            \
        : "+f"((c)[0]), "+f"((c)[1]), "+f"((c)[2]), "+f"((c)[3])           \
        : "r"(a0), "r"(a1), "r"(a2), "r"(a3), "r"(b0), "r"(b1))

// ---------------- BN pass 1 ----------------
__global__ void bn_pass1(const float* __restrict__ x) {
    int col = blockIdx.x * 256 + threadIdx.x;
    int r0  = blockIdx.y * (BATCH / RCHUNKS);
    float s = 0.f, ss = 0.f;
    #pragma unroll 4
    for (int r = 0; r < BATCH / RCHUNKS; r++) {
        float v = x[(size_t)(r0 + r) * FEAT + col];
        s += v; ss += v * v;
    }
    g_psum[blockIdx.y * FEAT + col]   = s;
    g_psumsq[blockIdx.y * FEAT + col] = ss;
}

// ---------------- BN pass 2 ----------------
__global__ void bn_pass2(const float* __restrict__ gamma,
                         const float* __restrict__ beta) {
    int col = blockIdx.x * blockDim.x + threadIdx.x;
    float s = 0.f, ss = 0.f;
    #pragma unroll
    for (int c = 0; c < RCHUNKS; c++) {
        s  += g_psum[c * FEAT + col];
        ss += g_psumsq[c * FEAT + col];
    }
    float mean = s * (1.f / BATCH);
    float var  = ss * (1.f / BATCH) - mean * mean;
    float rstd = rsqrtf(var + EPS);
    float a = rstd * gamma[col];
    g_scale[col] = a;
    g_shift[col] = beta[col] - mean * a;
}

// ---------------- xn -> fp16 (BN fused), 8 elems/thread (R11-best) --------
__global__ void xn_fp16(const float* __restrict__ x) {
    int i = blockIdx.x * 256 + threadIdx.x;
    size_t e = (size_t)i * 8;
    int col = (int)(e & 4095);
    float4 v0 = *(const float4*)(x + e);
    float4 v1 = *(const float4*)(x + e + 4);
    float4 sc0 = *(const float4*)(g_scale + col);
    float4 sc1 = *(const float4*)(g_scale + col + 4);
    float4 sh0 = *(const float4*)(g_shift + col);
    float4 sh1 = *(const float4*)(g_shift + col + 4);
    uint4 o;
    o.x = hpack(fmaf(v0.x, sc0.x, sh0.x), fmaf(v0.y, sc0.y, sh0.y));
    o.y = hpack(fmaf(v0.z, sc0.z, sh0.z), fmaf(v0.w, sc0.w, sh0.w));
    o.z = hpack(fmaf(v1.x, sc1.x, sh1.x), fmaf(v1.y, sc1.y, sh1.y));
    o.w = hpack(fmaf(v1.z, sc1.z, sh1.z), fmaf(v1.w, sc1.w, sh1.w));
    *(uint4*)(g_xnh + e / 2) = o;
}

// ---------------- W -> fp16 (WQ scaled by QPRE) ----------------
__global__ void w_fp16(const float* __restrict__ wq,
                       const float* __restrict__ wk,
                       const float* __restrict__ wv) {
    int i = blockIdx.x * 256 + threadIdx.x;    // pair index, 3*32768 total
    int w = i >> 15;
    int idx = i & 32767;
    const float* src = (w == 0) ? wq : (w == 1) ? wk : wv;
    float2 v = ((const float2*)src)[idx];
    float s = (w == 0) ? QPRE : 1.f;
    g_wh[i] = hpack(v.x * s, v.y * s);
}

// ---------------- fp16 cp.async QKV GEMM, 512 threads ----------------
// grid (3, 512). 512 thr = 16 warps (4m x 4n), warp tile m32 x n64.
// BK=32 (8 chunks), 4-stage cp.async ring, ONE sync per chunk.
#define GP    20                          // uint32 pitch per row
#define A_STG (128 * GP)
#define B_STG (256 * GP)
#define NSTG  4
#define SMEM_GEMM ((A_STG + B_STG) * NSTG * 4)   // 122880 bytes

__global__ void __launch_bounds__(512, 1) gemm_mma(
    const float* __restrict__ bq, const float* __restrict__ bk_,
    const float* __restrict__ bv)
{
    extern __shared__ uint32_t smu[];
    const int tid = threadIdx.x;
    const int w   = blockIdx.x;
    const int m0  = blockIdx.y * 128;

    const float* bias = (w == 0) ? bq : (w == 1) ? bk_ : bv;
    uint32_t*    outp = (w == 0) ? g_qh : (w == 1) ? g_kh : g_vh;
    const float  bs   = (w == 0) ? QPRE : 1.f;

    const int lane = tid & 31, wid = tid >> 5;
    const int wm = wid >> 2, wn = wid & 3;     // 4 x 4 warps
    const int g4 = lane >> 2, l4 = lane & 3;

    const uint32_t* asrc = g_xnh + (size_t)m0 * 128;
    const uint32_t* bsrc = g_wh + w * 32768;
    uint32_t sbase = (uint32_t)__cvta_generic_to_shared(smu);

    auto ISSUE = [&](int c, int st) {
        {
            int row = tid >> 2, seg = tid & 3;
            cp16(sbase + (st * A_STG + row * GP + seg * 4) * 4,
                 asrc + (size_t)row * 128 + c * 16 + seg * 4);
        }
        #pragma unroll
        for (int t = 0; t < 2; t++) {
            int i = tid + t * 512;
            int row = i >> 2, seg = i & 3;
            cp16(sbase + (NSTG * A_STG + st * B_STG + row * GP + seg * 4) * 4,
                 bsrc + (size_t)row * 128 + c * 16 + seg * 4);
        }
        asm volatile("cp.async.commit_group;" ::: "memory");
    };

    float acc[2][8][4];
    #pragma unroll
    for (int tm = 0; tm < 2; tm++)
        #pragma unroll
        for (int nt = 0; nt < 8; nt++)
            #pragma unroll
            for (int i = 0; i < 4; i++) acc[tm][nt][i] = 0.f;

    ISSUE(0, 0); ISSUE(1, 1); ISSUE(2, 2);

    #pragma unroll 1
    for (int c = 0; c < 8; c++) {
        if (c < 6) {
            asm volatile("cp.async.wait_group 2;" ::: "memory");
        } else {
            asm volatile("cp.async.wait_group 0;" ::: "memory");
        }
        __syncthreads();
        // Safe to prefetch chunk c+3 now: it overwrites stage (c-1)&3, which
        // every warp finished reading before the barrier above.
        if (c < 5) ISSUE(c + 3, (c + 3) & 3);
        const int st = c & 3;
        const uint32_t* A0 = smu + st * A_STG + (wm * 32) * GP;
        const uint32_t* B0 = smu + NSTG * A_STG + st * B_STG + (wn * 64) * GP;
        #pragma unroll
        for (int kk = 0; kk < 2; kk++) {
            uint32_t af[2][4];
            #pragma unroll
            for (int tm = 0; tm < 2; tm++) {
                int r = tm * 16 + g4;
                af[tm][0] = A0[r * GP + kk * 8 + l4];
                af[tm][1] = A0[(r + 8) * GP + kk * 8 + l4];
                af[tm][2] = A0[r * GP + kk * 8 + l4 + 4];
                af[tm][3] = A0[(r + 8) * GP + kk * 8 + l4 + 4];
            }
            #pragma unroll
            for (int nt = 0; nt < 8; nt++) {
                uint32_t fb0 = B0[(nt * 8 + g4) * GP + kk * 8 + l4];
                uint32_t fb1 = B0[(nt * 8 + g4) * GP + kk * 8 + l4 + 4];
                #pragma unroll
                for (int tm = 0; tm < 2; tm++)
                    MMA_FP16(acc[tm][nt], af[tm][0], af[tm][1],
                             af[tm][2], af[tm][3], fb0, fb1);
            }
        }
    }

    // ---- epilogue: bias add (scaled), pack fp16, store ----
    const int rbase = m0 + wm * 32;
    const int cbase = wn * 64;
    #pragma unroll
    for (int tm = 0; tm < 2; tm++) {
        int r = rbase + tm * 16 + g4;
        #pragma unroll
        for (int nt = 0; nt < 8; nt++) {
            int col = cbase + nt * 8 + l4 * 2;
            float2 bb = *(const float2*)(bias + col);
            float bx = bb.x * bs, by = bb.y * bs;
            outp[(size_t)r * 128 + (col >> 1)] =
                hpack(acc[tm][nt][0] + bx, acc[tm][nt][1] + by);
            outp[(size_t)(r + 8) * 128 + (col >> 1)] =
                hpack(acc[tm][nt][2] + bx, acc[tm][nt][3] + by);
        }
    }
}

// ---------------- fp16 tensor-core attention, 128-thr CTA, 2/batch --------
#define APITCH 12
#define VPITCH 132
#define SMEM_ATTN ((128 + 256) * APITCH * 4 + 16 * VPITCH * 4)   // 26880 B

__global__ void __launch_bounds__(128) attn_tc(const float* __restrict__ x,
                                               float* __restrict__ out)
{
    extern __shared__ uint32_t smq[];
    uint32_t* Qt = smq;                    // [128 e][p-pair] fp16x2 (pre-scaled)
    uint32_t* Kt = smq + 128 * APITCH;     // [256 f][p-pair]
    uint32_t* Vh = smq + (128 + 256) * APITCH;   // [16 p][f-pair]

    const int b    = blockIdx.x;
    const int half = blockIdx.y;
    const int tid  = threadIdx.x;
    const int lane = tid & 31, wid = tid >> 5;
    const int g4 = lane >> 2, l4 = lane & 3;

    // ---- Q (this half) + K (full): load fp16 rows, transpose via prmt ----
    {
        const int j  = tid & 7;                 // p-pair
        const int e0 = (tid >> 3) * 8;          // local e base
        {
            const uint32_t* q0 = g_qh + ((size_t)b * 16 + 2 * j) * 128
                                 + half * 64 + (e0 >> 1);
            uint4 qa = *(const uint4*)q0;
            uint4 qb = *(const uint4*)(q0 + 128);
            uint32_t av4[4] = {qa.x, qa.y, qa.z, qa.w};
            uint32_t bv4[4] = {qb.x, qb.y, qb.z, qb.w};
            #pragma unroll
            for (int i = 0; i < 4; i++) {
                Qt[(e0 + 2 * i) * APITCH + j]     = __byte_perm(av4[i], bv4[i], 0x5410);
                Qt[(e0 + 2 * i + 1) * APITCH + j] = __byte_perm(av4[i], bv4[i], 0x7632);
            }
        }
        #pragma unroll
        for (int r = 0; r < 2; r++) {
            int f0 = r * 128 + e0;
            const uint32_t* k0 = g_kh + ((size_t)b * 16 + 2 * j) * 128 + (f0 >> 1);
            uint4 ka = *(const uint4*)k0;
            uint4 kb = *(const uint4*)(k0 + 128);
            uint32_t av4[4] = {ka.x, ka.y, ka.z, ka.w};
            uint32_t bv4[4] = {kb.x, kb.y, kb.z, kb.w};
            #pragma unroll
            for (int i = 0; i < 4; i++) {
                Kt[(f0 + 2 * i) * APITCH + j]     = __byte_perm(av4[i], bv4[i], 0x5410);
                Kt[(f0 + 2 * i + 1) * APITCH + j] = __byte_perm(av4[i], bv4[i], 0x7632);
            }
        }
    }
    // ---- V: direct fp16 copy [p][f-pair] ----
    {
        const int p  = tid >> 3;
        const int t8 = (tid & 7) * 16;
        const uint4* vsrc = (const uint4*)(g_vh + ((size_t)b * 16 + p) * 128 + t8);
        uint4* vdst = (uint4*)(Vh + p * VPITCH + t8);
        vdst[0] = vsrc[0];
        vdst[1] = vsrc[1];
        vdst[2] = vsrc[2];
        vdst[3] = vsrc[3];
    }
    __syncthreads();

    // ---- persistent Q fragments (already QPRE-scaled) ----
    uint32_t af[2][4];
    #pragma unroll
    for (int tm = 0; tm < 2; tm++) {
        int eb = wid * 32 + tm * 16;
        af[tm][0] = Qt[(eb + g4) * APITCH + l4];
        af[tm][1] = Qt[(eb + g4 + 8) * APITCH + l4];
        af[tm][2] = Qt[(eb + g4) * APITCH + l4 + 4];
        af[tm][3] = Qt[(eb + g4 + 8) * APITCH + l4 + 4];
    }

    float av[2][2][4];
    #pragma unroll
    for (int tm = 0; tm < 2; tm++)
        #pragma unroll
        for (int np = 0; np < 2; np++)
            #pragma unroll
            for (int i = 0; i < 4; i++) av[tm][np][i] = 0.f;
    float srow[2][2] = {{0.f, 0.f}, {0.f, 0.f}};

    #pragma unroll 2
    for (int fc = 0; fc < 256; fc += 32) {
        float E[2][4][4];
        // ---- S: 4 n-tiles x 2 m-tiles ----
        #pragma unroll
        for (int nt = 0; nt < 4; nt++) {
            int f = fc + nt * 8 + g4;
            uint32_t kb0 = Kt[f * APITCH + l4];
            uint32_t kb1 = Kt[f * APITCH + l4 + 4];
            #pragma unroll
            for (int tm = 0; tm < 2; tm++) {
                float* c = E[tm][nt];
                c[0] = c[1] = c[2] = c[3] = 0.f;
                MMA_FP16(c, af[tm][0], af[tm][1], af[tm][2], af[tm][3],
                         kb0, kb1);
            }
        }
        // ---- exp2 + row sums ----
        #pragma unroll
        for (int tm = 0; tm < 2; tm++)
            #pragma unroll
            for (int nt = 0; nt < 4; nt++) {
                float* c = E[tm][nt];
                c[0] = ex2(c[0]);
                c[1] = ex2(c[1]);
                c[2] = ex2(c[2]);
                c[3] = ex2(c[3]);
                srow[tm][0] += c[0] + c[1];
                srow[tm][1] += c[2] + c[3];
            }
        // ---- AV: P(fp16) x V(fp16) ----
        #pragma unroll
        for (int s = 0; s < 2; s++) {
            uint32_t vb0[2], vb1[2];
            #pragma unroll
            for (int np = 0; np < 2; np++) {
                const uint32_t* vr = Vh + (np * 8 + g4) * VPITCH + (fc >> 1) + s * 8;
                vb0[np] = vr[l4];
                vb1[np] = vr[l4 + 4];
            }
            #pragma unroll
            for (int tm = 0; tm < 2; tm++) {
                uint32_t a0 = hpack(E[tm][2 * s][0], E[tm][2 * s][1]);
                uint32_t a1 = hpack(E[tm][2 * s][2], E[tm][2 * s][3]);
                uint32_t a2 = hpack(E[tm][2 * s + 1][0], E[tm][2 * s + 1][1]);
                uint32_t a3 = hpack(E[tm][2 * s + 1][2], E[tm][2 * s + 1][3]);
                #pragma unroll
                for (int np = 0; np < 2; np++)
                    MMA_FP16(av[tm][np], a0, a1, a2, a3, vb0[np], vb1[np]);
            }
        }
    }

    // ---- epilogue ----
    #pragma unroll
    for (int tm = 0; tm < 2; tm++) {
        float s0 = srow[tm][0];
        s0 += __shfl_xor_sync(0xffffffffu, s0, 1);
        s0 += __shfl_xor_sync(0xffffffffu, s0, 2);
        float s1 = srow[tm][1];
        s1 += __shfl_xor_sync(0xffffffffu, s1, 1);
        s1 += __shfl_xor_sync(0xffffffffu, s1, 2);
        float inv0 = 1.f / s0, inv1 = 1.f / s1;
        int e_lo = half * 128 + wid * 32 + tm * 16 + g4;
        #pragma unroll
        for (int np = 0; np < 2; np++) {
            int p = np * 8 + l4 * 2;
            size_t lo = (size_t)b * FEAT + e_lo * 16 + p;
            size_t hi = lo + 8 * 16;
            float2 x0 = *(const float2*)(x + lo);
            float2 x1 = *(const float2*)(x + hi);
            *(float2*)(out + lo) = make_float2(av[tm][np][0] * inv0 + x0.x,
                                               av[tm][np][1] * inv0 + x0.y);
            *(float2*)(out + hi) = make_float2(av[tm][np][2] * inv1 + x1.x,
                                               av[tm][np][3] * inv1 + x1.y);
        }
    }
}

// ---------------- launcher ----------------
extern "C" void kernel_launch(void* const* d_in, const int* in_sizes, int n_in,
                              void* d_out, int out_size) {
    const float* x     = (const float*)d_in[0];
    const float* WQ_w  = (const float*)d_in[1];
    const float* WQ_b  = (const float*)d_in[2];
    const float* WK_w  = (const float*)d_in[3];
    const float* WK_b  = (const float*)d_in[4];
    const float* WV_w  = (const float*)d_in[5];
    const float* WV_b  = (const float*)d_in[6];
    const float* gamma = (const float*)d_in[7];
    const float* beta  = (const float*)d_in[8];
    float* out = (float*)d_out;

    cudaFuncSetAttribute(gemm_mma, cudaFuncAttributeMaxDynamicSharedMemorySize,
                         SMEM_GEMM);
    cudaFuncSetAttribute(attn_tc, cudaFuncAttributeMaxDynamicSharedMemorySize,
                         SMEM_ATTN);

    bn_pass1<<<dim3(FEAT / 256, RCHUNKS), 256>>>(x);
    w_fp16<<<384, 256>>>(WQ_w, WK_w, WV_w);
    bn_pass2<<<FEAT / 256, 256>>>(gamma, beta);
    xn_fp16<<<(MROWS * 256 / 8) / 256, 256>>>(x);
    gemm_mma<<<dim3(3, 512), 512, SMEM_GEMM>>>(WQ_b, WK_b, WV_b);
    attn_tc<<<dim3(BATCH, 2), 128, SMEM_ATTN>>>(x, out);
}

// round 14
// speedup vs baseline: 1.0529x; 1.0157x over previous
#include <cuda_runtime.h>
#include <stdint.h>

// Problem constants
#define BATCH 4096
#define FEAT  4096
#define NP    16
#define DDIM  256
#define MROWS (BATCH * NP)   // 65536
#define EPS   1e-5f
#define QPRE   0.09017131f   // (1/sqrt(256)) * log2(e)

// ---------------- device scratch ----------------
#define RCHUNKS 64
__device__ float g_psum[RCHUNKS * FEAT];
__device__ float g_psumsq[RCHUNKS * FEAT];
__device__ float g_scale[FEAT];
__device__ float g_shift[FEAT];
__device__ uint32_t g_xnh[(size_t)MROWS * 128];  // BN(x) fp16x2, 32 MB
__device__ uint32_t g_wh[3 * 256 * 128];          // weights fp16x2 (WQ pre-scaled)
__device__ uint32_t g_qh[(size_t)MROWS * 128];    // Q' fp16x2
__device__ uint32_t g_kh[(size_t)MROWS * 128];
__device__ uint32_t g_vh[(size_t)MROWS * 128];

__device__ __forceinline__ uint32_t hpack(float y0, float y1) {
    uint32_t h;
    asm("cvt.rn.f16x2.f32 %0, %1, %2;" : "=r"(h) : "f"(y1), "f"(y0));
    return h;
}
__device__ __forceinline__ float ex2(float x) {
    float r;
    asm("ex2.approx.f32 %0, %1;" : "=f"(r) : "f"(x));
    return r;
}
__device__ __forceinline__ void cp16(uint32_t daddr, const void* src) {
    asm volatile("cp.async.cg.shared.global [%0], [%1], 16;"
                 :: "r"(daddr), "l"(src) : "memory");
}

#define MMA_FP16(c, a0, a1, a2, a3, b0, b1)                                \
    asm volatile(                                                          \
        "mma.sync.aligned.m16n8k16.row.col.f32.f16.f16.f32 "               \
        "{%0,%1,%2,%3}, {%4,%5,%6,%7}, {%8,%9}, {%0,%1,%2,%3};"            \
        : "+f"((c)[0]), "+f"((c)[1]), "+f"((c)[2]), "+f"((c)[3])           \
        : "r"(a0), "r"(a1), "r"(a2), "r"(a3), "r"(b0), "r"(b1))

// ---------------- BN pass 1 ----------------
__global__ void bn_pass1(const float* __restrict__ x) {
    int col = blockIdx.x * 256 + threadIdx.x;
    int r0  = blockIdx.y * (BATCH / RCHUNKS);
    float s = 0.f, ss = 0.f;
    #pragma unroll 4
    for (int r = 0; r < BATCH / RCHUNKS; r++) {
        float v = x[(size_t)(r0 + r) * FEAT + col];
        s += v; ss += v * v;
    }
    g_psum[blockIdx.y * FEAT + col]   = s;
    g_psumsq[blockIdx.y * FEAT + col] = ss;
}

// ---------------- BN pass 2 ----------------
__global__ void bn_pass2(const float* __restrict__ gamma,
                         const float* __restrict__ beta) {
    int col = blockIdx.x * blockDim.x + threadIdx.x;
    float s = 0.f, ss = 0.f;
    #pragma unroll
    for (int c = 0; c < RCHUNKS; c++) {
        s  += g_psum[c * FEAT + col];
        ss += g_psumsq[c * FEAT + col];
    }
    float mean = s * (1.f / BATCH);
    float var  = ss * (1.f / BATCH) - mean * mean;
    float rstd = rsqrtf(var + EPS);
    float a = rstd * gamma[col];
    g_scale[col] = a;
    g_shift[col] = beta[col] - mean * a;
}

// ---------------- xn -> fp16 (BN fused), 8 elems/thread ----------------
__global__ void xn_fp16(const float* __restrict__ x) {
    int i = blockIdx.x * 256 + threadIdx.x;
    size_t e = (size_t)i * 8;
    int col = (int)(e & 4095);
    float4 v0 = *(const float4*)(x + e);
    float4 v1 = *(const float4*)(x + e + 4);
    float4 sc0 = *(const float4*)(g_scale + col);
    float4 sc1 = *(const float4*)(g_scale + col + 4);
    float4 sh0 = *(const float4*)(g_shift + col);
    float4 sh1 = *(const float4*)(g_shift + col + 4);
    uint4 o;
    o.x = hpack(fmaf(v0.x, sc0.x, sh0.x), fmaf(v0.y, sc0.y, sh0.y));
    o.y = hpack(fmaf(v0.z, sc0.z, sh0.z), fmaf(v0.w, sc0.w, sh0.w));
    o.z = hpack(fmaf(v1.x, sc1.x, sh1.x), fmaf(v1.y, sc1.y, sh1.y));
    o.w = hpack(fmaf(v1.z, sc1.z, sh1.z), fmaf(v1.w, sc1.w, sh1.w));
    *(uint4*)(g_xnh + e / 2) = o;
}

// ---------------- W -> fp16 (WQ scaled by QPRE) ----------------
__global__ void w_fp16(const float* __restrict__ wq,
                       const float* __restrict__ wk,
                       const float* __restrict__ wv) {
    int i = blockIdx.x * 256 + threadIdx.x;
    int w = i >> 15;
    int idx = i & 32767;
    const float* src = (w == 0) ? wq : (w == 1) ? wk : wv;
    float2 v = ((const float2*)src)[idx];
    float s = (w == 0) ? QPRE : 1.f;
    g_wh[i] = hpack(v.x * s, v.y * s);
}

// ---------------- fp16 cp.async QKV GEMM, 512 threads, BK=64 --------------
// grid (3, 512). 16 warps (4m x 4n), warp tile m32 x n64.
// BK=64 (4 chunks), 3-stage cp.async ring, ONE sync per chunk.
#define GP    36                          // uint32 pitch per row (32 + 4 pad)
#define A_STG (128 * GP)
#define B_STG (256 * GP)
#define NSTG  3
#define SMEM_GEMM ((A_STG + B_STG) * NSTG * 4)   // 165888 bytes

__global__ void __launch_bounds__(512, 1) gemm_mma(
    const float* __restrict__ bq, const float* __restrict__ bk_,
    const float* __restrict__ bv)
{
    extern __shared__ uint32_t smu[];
    const int tid = threadIdx.x;
    const int w   = blockIdx.x;
    const int m0  = blockIdx.y * 128;

    const float* bias = (w == 0) ? bq : (w == 1) ? bk_ : bv;
    uint32_t*    outp = (w == 0) ? g_qh : (w == 1) ? g_kh : g_vh;
    const float  bs   = (w == 0) ? QPRE : 1.f;

    const int lane = tid & 31, wid = tid >> 5;
    const int wm = wid >> 2, wn = wid & 3;     // 4 x 4 warps
    const int g4 = lane >> 2, l4 = lane & 3;

    const uint32_t* asrc = g_xnh + (size_t)m0 * 128;
    const uint32_t* bsrc = g_wh + w * 32768;
    uint32_t sbase = (uint32_t)__cvta_generic_to_shared(smu);

    auto ISSUE = [&](int c, int st) {
        // A: 128 rows x 8 segs (128B/row) = 1024 cp16; 2 per thread
        #pragma unroll
        for (int t = 0; t < 2; t++) {
            int i = tid + t * 512;
            int row = i >> 3, seg = i & 7;
            cp16(sbase + (st * A_STG + row * GP + seg * 4) * 4,
                 asrc + (size_t)row * 128 + c * 32 + seg * 4);
        }
        // B: 256 rows x 8 segs = 2048 cp16; 4 per thread
        #pragma unroll
        for (int t = 0; t < 4; t++) {
            int i = tid + t * 512;
            int row = i >> 3, seg = i & 7;
            cp16(sbase + (NSTG * A_STG + st * B_STG + row * GP + seg * 4) * 4,
                 bsrc + (size_t)row * 128 + c * 32 + seg * 4);
        }
        asm volatile("cp.async.commit_group;" ::: "memory");
    };

    float acc[2][8][4];
    #pragma unroll
    for (int tm = 0; tm < 2; tm++)
        #pragma unroll
        for (int nt = 0; nt < 8; nt++)
            #pragma unroll
            for (int i = 0; i < 4; i++) acc[tm][nt][i] = 0.f;

    ISSUE(0, 0); ISSUE(1, 1);

    #pragma unroll 1
    for (int c = 0; c < 4; c++) {
        if (c < 3) {
            asm volatile("cp.async.wait_group 1;" ::: "memory");
        } else {
            asm volatile("cp.async.wait_group 0;" ::: "memory");
        }
        __syncthreads();
        // Prefetch chunk c+2 into stage (c+2)%3 = (c-1)%3 (consumed last chunk).
        if (c < 2) ISSUE(c + 2, (c + 2) % 3);
        const int st = c % 3;
        const uint32_t* A0 = smu + st * A_STG + (wm * 32) * GP;
        const uint32_t* B0 = smu + NSTG * A_STG + st * B_STG + (wn * 64) * GP;
        #pragma unroll
        for (int kk = 0; kk < 4; kk++) {
            uint32_t af[2][4];
            #pragma unroll
            for (int tm = 0; tm < 2; tm++) {
                int r = tm * 16 + g4;
                af[tm][0] = A0[r * GP + kk * 8 + l4];
                af[tm][1] = A0[(r + 8) * GP + kk * 8 + l4];
                af[tm][2] = A0[r * GP + kk * 8 + l4 + 4];
                af[tm][3] = A0[(r + 8) * GP + kk * 8 + l4 + 4];
            }
            #pragma unroll
            for (int nt = 0; nt < 8; nt++) {
                uint32_t fb0 = B0[(nt * 8 + g4) * GP + kk * 8 + l4];
                uint32_t fb1 = B0[(nt * 8 + g4) * GP + kk * 8 + l4 + 4];
                #pragma unroll
                for (int tm = 0; tm < 2; tm++)
                    MMA_FP16(acc[tm][nt], af[tm][0], af[tm][1],
                             af[tm][2], af[tm][3], fb0, fb1);
            }
        }
    }

    // ---- epilogue: bias add (scaled), pack fp16, store ----
    const int rbase = m0 + wm * 32;
    const int cbase = wn * 64;
    #pragma unroll
    for (int tm = 0; tm < 2; tm++) {
        int r = rbase + tm * 16 + g4;
        #pragma unroll
        for (int nt = 0; nt < 8; nt++) {
            int col = cbase + nt * 8 + l4 * 2;
            float2 bb = *(const float2*)(bias + col);
            float bx = bb.x * bs, by = bb.y * bs;
            outp[(size_t)r * 128 + (col >> 1)] =
                hpack(acc[tm][nt][0] + bx, acc[tm][nt][1] + by);
            outp[(size_t)(r + 8) * 128 + (col >> 1)] =
                hpack(acc[tm][nt][2] + bx, acc[tm][nt][3] + by);
        }
    }
}

// ---------------- fp16 tensor-core attention, 128-thr CTA, 2/batch --------
// Row sums via ones-column mma: V extended with n8-tile (row16=1, 17-23=0).
#define APITCH 12
#define VPITCH 132
#define SMEM_ATTN ((128 + 256) * APITCH * 4 + 24 * VPITCH * 4)   // 31104 B

__global__ void __launch_bounds__(128) attn_tc(const float* __restrict__ x,
                                               float* __restrict__ out)
{
    extern __shared__ uint32_t smq[];
    uint32_t* Qt = smq;                    // [128 e][p-pair] fp16x2 (pre-scaled)
    uint32_t* Kt = smq + 128 * APITCH;     // [256 f][p-pair]
    uint32_t* Vh = smq + (128 + 256) * APITCH;   // [24 p][f-pair]

    const int b    = blockIdx.x;
    const int half = blockIdx.y;
    const int tid  = threadIdx.x;
    const int lane = tid & 31, wid = tid >> 5;
    const int g4 = lane >> 2, l4 = lane & 3;

    // ---- Q (this half) + K (full): load fp16 rows, transpose via prmt ----
    {
        const int j  = tid & 7;                 // p-pair
        const int e0 = (tid >> 3) * 8;          // local e base
        {
            const uint32_t* q0 = g_qh + ((size_t)b * 16 + 2 * j) * 128
                                 + half * 64 + (e0 >> 1);
            uint4 qa = *(const uint4*)q0;
            uint4 qb = *(const uint4*)(q0 + 128);
            uint32_t av4[4] = {qa.x, qa.y, qa.z, qa.w};
            uint32_t bv4[4] = {qb.x, qb.y, qb.z, qb.w};
            #pragma unroll
            for (int i = 0; i < 4; i++) {
                Qt[(e0 + 2 * i) * APITCH + j]     = __byte_perm(av4[i], bv4[i], 0x5410);
                Qt[(e0 + 2 * i + 1) * APITCH + j] = __byte_perm(av4[i], bv4[i], 0x7632);
            }
        }
        #pragma unroll
        for (int r = 0; r < 2; r++) {
            int f0 = r * 128 + e0;
            const uint32_t* k0 = g_kh + ((size_t)b * 16 + 2 * j) * 128 + (f0 >> 1);
            uint4 ka = *(const uint4*)k0;
            uint4 kb = *(const uint4*)(k0 + 128);
            uint32_t av4[4] = {ka.x, ka.y, ka.z, ka.w};
            uint32_t bv4[4] = {kb.x, kb.y, kb.z, kb.w};
            #pragma unroll
            for (int i = 0; i < 4; i++) {
                Kt[(f0 + 2 * i) * APITCH + j]     = __byte_perm(av4[i], bv4[i], 0x5410);
                Kt[(f0 + 2 * i + 1) * APITCH + j] = __byte_perm(av4[i], bv4[i], 0x7632);
            }
        }
    }
    // ---- V: direct fp16 copy [p][f-pair]; rows 16-23 = ones-tile ----
    {
        const int p  = tid >> 3;
        const int t8 = (tid & 7) * 16;
        const uint4* vsrc = (const uint4*)(g_vh + ((size_t)b * 16 + p) * 128 + t8);
        uint4* vdst = (uint4*)(Vh + p * VPITCH + t8);
        vdst[0] = vsrc[0];
        vdst[1] = vsrc[1];
        vdst[2] = vsrc[2];
        vdst[3] = vsrc[3];
        // ones-tile: row 16 = fp16 1.0 pairs, rows 17-23 = 0
        int p2 = 16 + (tid >> 4);              // 16..23
        int s8 = (tid & 15) * 8;               // 8 uints per thread
        uint32_t fill = (p2 == 16) ? 0x3C003C00u : 0u;
        uint32_t* d2 = Vh + p2 * VPITCH + s8;
        #pragma unroll
        for (int i = 0; i < 8; i++) d2[i] = fill;
    }
    __syncthreads();

    // ---- persistent Q fragments (already QPRE-scaled) ----
    uint32_t af[2][4];
    #pragma unroll
    for (int tm = 0; tm < 2; tm++) {
        int eb = wid * 32 + tm * 16;
        af[tm][0] = Qt[(eb + g4) * APITCH + l4];
        af[tm][1] = Qt[(eb + g4 + 8) * APITCH + l4];
        af[tm][2] = Qt[(eb + g4) * APITCH + l4 + 4];
        af[tm][3] = Qt[(eb + g4 + 8) * APITCH + l4 + 4];
    }

    float av[2][3][4];
    #pragma unroll
    for (int tm = 0; tm < 2; tm++)
        #pragma unroll
        for (int np = 0; np < 3; np++)
            #pragma unroll
            for (int i = 0; i < 4; i++) av[tm][np][i] = 0.f;

    #pragma unroll 2
    for (int fc = 0; fc < 256; fc += 32) {
        float E[2][4][4];
        // ---- S: 4 n-tiles x 2 m-tiles ----
        #pragma unroll
        for (int nt = 0; nt < 4; nt++) {
            int f = fc + nt * 8 + g4;
            uint32_t kb0 = Kt[f * APITCH + l4];
            uint32_t kb1 = Kt[f * APITCH + l4 + 4];
            #pragma unroll
            for (int tm = 0; tm < 2; tm++) {
                float* c = E[tm][nt];
                c[0] = c[1] = c[2] = c[3] = 0.f;
                MMA_FP16(c, af[tm][0], af[tm][1], af[tm][2], af[tm][3],
                         kb0, kb1);
            }
        }
        // ---- exp2 (row sums now via ones-column mma) ----
        #pragma unroll
        for (int tm = 0; tm < 2; tm++)
            #pragma unroll
            for (int nt = 0; nt < 4; nt++) {
                float* c = E[tm][nt];
                c[0] = ex2(c[0]);
                c[1] = ex2(c[1]);
                c[2] = ex2(c[2]);
                c[3] = ex2(c[3]);
            }
        // ---- AV: P(fp16) x V(fp16), 3rd n-tile = ones column ----
        #pragma unroll
        for (int s = 0; s < 2; s++) {
            uint32_t vb0[3], vb1[3];
            #pragma unroll
            for (int np = 0; np < 3; np++) {
                const uint32_t* vr = Vh + (np * 8 + g4) * VPITCH + (fc >> 1) + s * 8;
                vb0[np] = vr[l4];
                vb1[np] = vr[l4 + 4];
            }
            #pragma unroll
            for (int tm = 0; tm < 2; tm++) {
                uint32_t a0 = hpack(E[tm][2 * s][0], E[tm][2 * s][1]);
                uint32_t a1 = hpack(E[tm][2 * s][2], E[tm][2 * s][3]);
                uint32_t a2 = hpack(E[tm][2 * s + 1][0], E[tm][2 * s + 1][1]);
                uint32_t a3 = hpack(E[tm][2 * s + 1][2], E[tm][2 * s + 1][3]);
                #pragma unroll
                for (int np = 0; np < 3; np++)
                    MMA_FP16(av[tm][np], a0, a1, a2, a3, vb0[np], vb1[np]);
            }
        }
    }

    // ---- epilogue: row sums live in av[tm][2][0]/[2] on l4==0 lanes ----
    #pragma unroll
    for (int tm = 0; tm < 2; tm++) {
        int src = (lane >> 2) << 2;            // lane with same g4, l4=0
        float s0 = __shfl_sync(0xffffffffu, av[tm][2][0], src);
        float s1 = __shfl_sync(0xffffffffu, av[tm][2][2], src);
        float inv0 = 1.f / s0, inv1 = 1.f / s1;
        int e_lo = half * 128 + wid * 32 + tm * 16 + g4;
        #pragma unroll
        for (int np = 0; np < 2; np++) {
            int p = np * 8 + l4 * 2;
            size_t lo = (size_t)b * FEAT + e_lo * 16 + p;
            size_t hi = lo + 8 * 16;
            float2 x0 = *(const float2*)(x + lo);
            float2 x1 = *(const float2*)(x + hi);
            *(float2*)(out + lo) = make_float2(av[tm][np][0] * inv0 + x0.x,
                                               av[tm][np][1] * inv0 + x0.y);
            *(float2*)(out + hi) = make_float2(av[tm][np][2] * inv1 + x1.x,
                                               av[tm][np][3] * inv1 + x1.y);
        }
    }
}

// ---------------- launcher ----------------
extern "C" void kernel_launch(void* const* d_in, const int* in_sizes, int n_in,
                              void* d_out, int out_size) {
    const float* x     = (const float*)d_in[0];
    const float* WQ_w  = (const float*)d_in[1];
    const float* WQ_b  = (const float*)d_in[2];
    const float* WK_w  = (const float*)d_in[3];
    const float* WK_b  = (const float*)d_in[4];
    const float* WV_w  = (const float*)d_in[5];
    const float* WV_b  = (const float*)d_in[6];
    const float* gamma = (const float*)d_in[7];
    const float* beta  = (const float*)d_in[8];
    float* out = (float*)d_out;

    cudaFuncSetAttribute(gemm_mma, cudaFuncAttributeMaxDynamicSharedMemorySize,
                         SMEM_GEMM);
    cudaFuncSetAttribute(attn_tc, cudaFuncAttributeMaxDynamicSharedMemorySize,
                         SMEM_ATTN);

    bn_pass1<<<dim3(FEAT / 256, RCHUNKS), 256>>>(x);
    w_fp16<<<384, 256>>>(WQ_w, WK_w, WV_w);
    bn_pass2<<<FEAT / 256, 256>>>(gamma, beta);
    xn_fp16<<<(MROWS * 256 / 8) / 256, 256>>>(x);
    gemm_mma<<<dim3(3, 512), 512, SMEM_GEMM>>>(WQ_b, WK_b, WV_b);
    attn_tc<<<dim3(BATCH, 2), 128, SMEM_ATTN>>>(x, out);
}

// round 15
// speedup vs baseline: 1.0582x; 1.0050x over previous
#include <cuda_runtime.h>
#include <stdint.h>

// Problem constants
#define BATCH 4096
#define FEAT  4096
#define NP    16
#define DDIM  256
#define MROWS (BATCH * NP)   // 65536
#define EPS   1e-5f
#define QPRE   0.09017131f   // (1/sqrt(256)) * log2(e)

// ---------------- device scratch ----------------
#define RCHUNKS 128
__device__ float g_psum[RCHUNKS * FEAT];
__device__ float g_psumsq[RCHUNKS * FEAT];
__device__ float g_scale[FEAT];
__device__ float g_shift[FEAT];
__device__ uint32_t g_xnh[(size_t)MROWS * 128];  // BN(x) fp16x2, 32 MB
__device__ uint32_t g_wh[3 * 256 * 128];          // weights fp16x2 (WQ pre-scaled)
__device__ uint32_t g_qh[(size_t)MROWS * 128];    // Q' fp16x2
__device__ uint32_t g_kh[(size_t)MROWS * 128];
__device__ uint32_t g_vh[(size_t)MROWS * 128];

__device__ __forceinline__ uint32_t hpack(float y0, float y1) {
    uint32_t h;
    asm("cvt.rn.f16x2.f32 %0, %1, %2;" : "=r"(h) : "f"(y1), "f"(y0));
    return h;
}
__device__ __forceinline__ uint32_t hex2(uint32_t h) {
    uint32_t r;
    asm("ex2.approx.f16x2 %0, %1;" : "=r"(r) : "r"(h));
    return r;
}
__device__ __forceinline__ void cp16(uint32_t daddr, const void* src) {
    asm volatile("cp.async.cg.shared.global [%0], [%1], 16;"
                 :: "r"(daddr), "l"(src) : "memory");
}

#define MMA_FP16(c, a0, a1, a2, a3, b0, b1)                                \
    asm volatile(                                                          \
        "mma.sync.aligned.m16n8k16.row.col.f32.f16.f16.f32 "               \
        "{%0,%1,%2,%3}, {%4,%5,%6,%7}, {%8,%9}, {%0,%1,%2,%3};"            \
        : "+f"((c)[0]), "+f"((c)[1]), "+f"((c)[2]), "+f"((c)[3])           \
        : "r"(a0), "r"(a1), "r"(a2), "r"(a3), "r"(b0), "r"(b1))

// ---------------- BN pass 1 ----------------
__global__ void bn_pass1(const float* __restrict__ x) {
    int col = blockIdx.x * 256 + threadIdx.x;
    int r0  = blockIdx.y * (BATCH / RCHUNKS);
    float s = 0.f, ss = 0.f;
    #pragma unroll 4
    for (int r = 0; r < BATCH / RCHUNKS; r++) {
        float v = x[(size_t)(r0 + r) * FEAT + col];
        s += v; ss += v * v;
    }
    g_psum[blockIdx.y * FEAT + col]   = s;
    g_psumsq[blockIdx.y * FEAT + col] = ss;
}

// ---------------- BN pass 2 ----------------
__global__ void bn_pass2(const float* __restrict__ gamma,
                         const float* __restrict__ beta) {
    int col = blockIdx.x * blockDim.x + threadIdx.x;
    float s = 0.f, ss = 0.f;
    #pragma unroll
    for (int c = 0; c < RCHUNKS; c++) {
        s  += g_psum[c * FEAT + col];
        ss += g_psumsq[c * FEAT + col];
    }
    float mean = s * (1.f / BATCH);
    float var  = ss * (1.f / BATCH) - mean * mean;
    float rstd = rsqrtf(var + EPS);
    float a = rstd * gamma[col];
    g_scale[col] = a;
    g_shift[col] = beta[col] - mean * a;
}

// ---------------- xn -> fp16 (BN fused), 8 elems/thread ----------------
__global__ void xn_fp16(const float* __restrict__ x) {
    int i = blockIdx.x * 256 + threadIdx.x;
    size_t e = (size_t)i * 8;
    int col = (int)(e & 4095);
    float4 v0 = *(const float4*)(x + e);
    float4 v1 = *(const float4*)(x + e + 4);
    float4 sc0 = *(const float4*)(g_scale + col);
    float4 sc1 = *(const float4*)(g_scale + col + 4);
    float4 sh0 = *(const float4*)(g_shift + col);
    float4 sh1 = *(const float4*)(g_shift + col + 4);
    uint4 o;
    o.x = hpack(fmaf(v0.x, sc0.x, sh0.x), fmaf(v0.y, sc0.y, sh0.y));
    o.y = hpack(fmaf(v0.z, sc0.z, sh0.z), fmaf(v0.w, sc0.w, sh0.w));
    o.z = hpack(fmaf(v1.x, sc1.x, sh1.x), fmaf(v1.y, sc1.y, sh1.y));
    o.w = hpack(fmaf(v1.z, sc1.z, sh1.z), fmaf(v1.w, sc1.w, sh1.w));
    *(uint4*)(g_xnh + e / 2) = o;
}

// ---------------- W -> fp16 (WQ scaled by QPRE) ----------------
__global__ void w_fp16(const float* __restrict__ wq,
                       const float* __restrict__ wk,
                       const float* __restrict__ wv) {
    int i = blockIdx.x * 256 + threadIdx.x;
    int w = i >> 15;
    int idx = i & 32767;
    const float* src = (w == 0) ? wq : (w == 1) ? wk : wv;
    float2 v = ((const float2*)src)[idx];
    float s = (w == 0) ? QPRE : 1.f;
    g_wh[i] = hpack(v.x * s, v.y * s);
}

// ---------------- fp16 cp.async QKV GEMM, 512 threads, BK=64 --------------
#define GP    36
#define A_STG (128 * GP)
#define B_STG (256 * GP)
#define NSTG  3
#define SMEM_GEMM ((A_STG + B_STG) * NSTG * 4)   // 165888 bytes

__global__ void __launch_bounds__(512, 1) gemm_mma(
    const float* __restrict__ bq, const float* __restrict__ bk_,
    const float* __restrict__ bv)
{
    extern __shared__ uint32_t smu[];
    const int tid = threadIdx.x;
    const int w   = blockIdx.x;
    const int m0  = blockIdx.y * 128;

    const float* bias = (w == 0) ? bq : (w == 1) ? bk_ : bv;
    uint32_t*    outp = (w == 0) ? g_qh : (w == 1) ? g_kh : g_vh;
    const float  bs   = (w == 0) ? QPRE : 1.f;

    const int lane = tid & 31, wid = tid >> 5;
    const int wm = wid >> 2, wn = wid & 3;
    const int g4 = lane >> 2, l4 = lane & 3;

    const uint32_t* asrc = g_xnh + (size_t)m0 * 128;
    const uint32_t* bsrc = g_wh + w * 32768;
    uint32_t sbase = (uint32_t)__cvta_generic_to_shared(smu);

    auto ISSUE = [&](int c, int st) {
        #pragma unroll
        for (int t = 0; t < 2; t++) {
            int i = tid + t * 512;
            int row = i >> 3, seg = i & 7;
            cp16(sbase + (st * A_STG + row * GP + seg * 4) * 4,
                 asrc + (size_t)row * 128 + c * 32 + seg * 4);
        }
        #pragma unroll
        for (int t = 0; t < 4; t++) {
            int i = tid + t * 512;
            int row = i >> 3, seg = i & 7;
            cp16(sbase + (NSTG * A_STG + st * B_STG + row * GP + seg * 4) * 4,
                 bsrc + (size_t)row * 128 + c * 32 + seg * 4);
        }
        asm volatile("cp.async.commit_group;" ::: "memory");
    };

    float acc[2][8][4];
    #pragma unroll
    for (int tm = 0; tm < 2; tm++)
        #pragma unroll
        for (int nt = 0; nt < 8; nt++)
            #pragma unroll
            for (int i = 0; i < 4; i++) acc[tm][nt][i] = 0.f;

    ISSUE(0, 0); ISSUE(1, 1);

    #pragma unroll 1
    for (int c = 0; c < 4; c++) {
        if (c < 3) {
            asm volatile("cp.async.wait_group 1;" ::: "memory");
        } else {
            asm volatile("cp.async.wait_group 0;" ::: "memory");
        }
        __syncthreads();
        if (c < 2) ISSUE(c + 2, (c + 2) % 3);
        const int st = c % 3;
        const uint32_t* A0 = smu + st * A_STG + (wm * 32) * GP;
        const uint32_t* B0 = smu + NSTG * A_STG + st * B_STG + (wn * 64) * GP;
        #pragma unroll
        for (int kk = 0; kk < 4; kk++) {
            uint32_t af[2][4];
            #pragma unroll
            for (int tm = 0; tm < 2; tm++) {
                int r = tm * 16 + g4;
                af[tm][0] = A0[r * GP + kk * 8 + l4];
                af[tm][1] = A0[(r + 8) * GP + kk * 8 + l4];
                af[tm][2] = A0[r * GP + kk * 8 + l4 + 4];
                af[tm][3] = A0[(r + 8) * GP + kk * 8 + l4 + 4];
            }
            #pragma unroll
            for (int nt = 0; nt < 8; nt++) {
                uint32_t fb0 = B0[(nt * 8 + g4) * GP + kk * 8 + l4];
                uint32_t fb1 = B0[(nt * 8 + g4) * GP + kk * 8 + l4 + 4];
                #pragma unroll
                for (int tm = 0; tm < 2; tm++)
                    MMA_FP16(acc[tm][nt], af[tm][0], af[tm][1],
                             af[tm][2], af[tm][3], fb0, fb1);
            }
        }
    }

    const int rbase = m0 + wm * 32;
    const int cbase = wn * 64;
    #pragma unroll
    for (int tm = 0; tm < 2; tm++) {
        int r = rbase + tm * 16 + g4;
        #pragma unroll
        for (int nt = 0; nt < 8; nt++) {
            int col = cbase + nt * 8 + l4 * 2;
            float2 bb = *(const float2*)(bias + col);
            float bx = bb.x * bs, by = bb.y * bs;
            outp[(size_t)r * 128 + (col >> 1)] =
                hpack(acc[tm][nt][0] + bx, acc[tm][nt][1] + by);
            outp[(size_t)(r + 8) * 128 + (col >> 1)] =
                hpack(acc[tm][nt][2] + bx, acc[tm][nt][3] + by);
        }
    }
}

// ---------------- fp16 tensor-core attention, f16x2 exp -------------------
// Row sums via ones-column mma; exp via ex2.approx.f16x2 (2 exps/MUFU-op).
#define APITCH 12
#define VPITCH 132
#define SMEM_ATTN ((128 + 256) * APITCH * 4 + 24 * VPITCH * 4)   // 31104 B

__global__ void __launch_bounds__(128) attn_tc(const float* __restrict__ x,
                                               float* __restrict__ out)
{
    extern __shared__ uint32_t smq[];
    uint32_t* Qt = smq;                    // [128 e][p-pair] fp16x2 (pre-scaled)
    uint32_t* Kt = smq + 128 * APITCH;     // [256 f][p-pair]
    uint32_t* Vh = smq + (128 + 256) * APITCH;   // [24 p][f-pair]

    const int b    = blockIdx.x;
    const int half = blockIdx.y;
    const int tid  = threadIdx.x;
    const int lane = tid & 31, wid = tid >> 5;
    const int g4 = lane >> 2, l4 = lane & 3;

    // ---- Q (this half) + K (full): load fp16 rows, transpose via prmt ----
    {
        const int j  = tid & 7;
        const int e0 = (tid >> 3) * 8;
        {
            const uint32_t* q0 = g_qh + ((size_t)b * 16 + 2 * j) * 128
                                 + half * 64 + (e0 >> 1);
            uint4 qa = *(const uint4*)q0;
            uint4 qb = *(const uint4*)(q0 + 128);
            uint32_t av4[4] = {qa.x, qa.y, qa.z, qa.w};
            uint32_t bv4[4] = {qb.x, qb.y, qb.z, qb.w};
            #pragma unroll
            for (int i = 0; i < 4; i++) {
                Qt[(e0 + 2 * i) * APITCH + j]     = __byte_perm(av4[i], bv4[i], 0x5410);
                Qt[(e0 + 2 * i + 1) * APITCH + j] = __byte_perm(av4[i], bv4[i], 0x7632);
            }
        }
        #pragma unroll
        for (int r = 0; r < 2; r++) {
            int f0 = r * 128 + e0;
            const uint32_t* k0 = g_kh + ((size_t)b * 16 + 2 * j) * 128 + (f0 >> 1);
            uint4 ka = *(const uint4*)k0;
            uint4 kb = *(const uint4*)(k0 + 128);
            uint32_t av4[4] = {ka.x, ka.y, ka.z, ka.w};
            uint32_t bv4[4] = {kb.x, kb.y, kb.z, kb.w};
            #pragma unroll
            for (int i = 0; i < 4; i++) {
                Kt[(f0 + 2 * i) * APITCH + j]     = __byte_perm(av4[i], bv4[i], 0x5410);
                Kt[(f0 + 2 * i + 1) * APITCH + j] = __byte_perm(av4[i], bv4[i], 0x7632);
            }
        }
    }
    // ---- V: direct fp16 copy [p][f-pair]; rows 16-23 = ones-tile ----
    {
        const int p  = tid >> 3;
        const int t8 = (tid & 7) * 16;
        const uint4* vsrc = (const uint4*)(g_vh + ((size_t)b * 16 + p) * 128 + t8);
        uint4* vdst = (uint4*)(Vh + p * VPITCH + t8);
        vdst[0] = vsrc[0];
        vdst[1] = vsrc[1];
        vdst[2] = vsrc[2];
        vdst[3] = vsrc[3];
        int p2 = 16 + (tid >> 4);
        int s8 = (tid & 15) * 8;
        uint32_t fill = (p2 == 16) ? 0x3C003C00u : 0u;
        uint32_t* d2 = Vh + p2 * VPITCH + s8;
        #pragma unroll
        for (int i = 0; i < 8; i++) d2[i] = fill;
    }
    __syncthreads();

    // ---- persistent Q fragments ----
    uint32_t af[2][4];
    #pragma unroll
    for (int tm = 0; tm < 2; tm++) {
        int eb = wid * 32 + tm * 16;
        af[tm][0] = Qt[(eb + g4) * APITCH + l4];
        af[tm][1] = Qt[(eb + g4 + 8) * APITCH + l4];
        af[tm][2] = Qt[(eb + g4) * APITCH + l4 + 4];
        af[tm][3] = Qt[(eb + g4 + 8) * APITCH + l4 + 4];
    }

    float av[2][3][4];
    #pragma unroll
    for (int tm = 0; tm < 2; tm++)
        #pragma unroll
        for (int np = 0; np < 3; np++)
            #pragma unroll
            for (int i = 0; i < 4; i++) av[tm][np][i] = 0.f;

    #pragma unroll 2
    for (int fc = 0; fc < 256; fc += 32) {
        float E[2][4][4];
        // ---- S: 4 n-tiles x 2 m-tiles ----
        #pragma unroll
        for (int nt = 0; nt < 4; nt++) {
            int f = fc + nt * 8 + g4;
            uint32_t kb0 = Kt[f * APITCH + l4];
            uint32_t kb1 = Kt[f * APITCH + l4 + 4];
            #pragma unroll
            for (int tm = 0; tm < 2; tm++) {
                float* c = E[tm][nt];
                c[0] = c[1] = c[2] = c[3] = 0.f;
                MMA_FP16(c, af[tm][0], af[tm][1], af[tm][2], af[tm][3],
                         kb0, kb1);
            }
        }
        // ---- pack S args to fp16x2, exp via f16x2 MUFU (2 exps/op) ----
        uint32_t Ppk[2][4][2];
        #pragma unroll
        for (int tm = 0; tm < 2; tm++)
            #pragma unroll
            for (int nt = 0; nt < 4; nt++) {
                float* c = E[tm][nt];
                Ppk[tm][nt][0] = hex2(hpack(c[0], c[1]));
                Ppk[tm][nt][1] = hex2(hpack(c[2], c[3]));
            }
        // ---- AV: P(fp16) x V(fp16), 3rd n-tile = ones column ----
        #pragma unroll
        for (int s = 0; s < 2; s++) {
            uint32_t vb0[3], vb1[3];
            #pragma unroll
            for (int np = 0; np < 3; np++) {
                const uint32_t* vr = Vh + (np * 8 + g4) * VPITCH + (fc >> 1) + s * 8;
                vb0[np] = vr[l4];
                vb1[np] = vr[l4 + 4];
            }
            #pragma unroll
            for (int tm = 0; tm < 2; tm++) {
                uint32_t a0 = Ppk[tm][2 * s][0];
                uint32_t a1 = Ppk[tm][2 * s][1];
                uint32_t a2 = Ppk[tm][2 * s + 1][0];
                uint32_t a3 = Ppk[tm][2 * s + 1][1];
                #pragma unroll
                for (int np = 0; np < 3; np++)
                    MMA_FP16(av[tm][np], a0, a1, a2, a3, vb0[np], vb1[np]);
            }
        }
    }

    // ---- epilogue: row sums live in av[tm][2][0]/[2] on l4==0 lanes ----
    #pragma unroll
    for (int tm = 0; tm < 2; tm++) {
        int src = (lane >> 2) << 2;
        float s0 = __shfl_sync(0xffffffffu, av[tm][2][0], src);
        float s1 = __shfl_sync(0xffffffffu, av[tm][2][2], src);
        float inv0 = 1.f / s0, inv1 = 1.f / s1;
        int e_lo = half * 128 + wid * 32 + tm * 16 + g4;
        #pragma unroll
        for (int np = 0; np < 2; np++) {
            int p = np * 8 + l4 * 2;
            size_t lo = (size_t)b * FEAT + e_lo * 16 + p;
            size_t hi = lo + 8 * 16;
            float2 x0 = *(const float2*)(x + lo);
            float2 x1 = *(const float2*)(x + hi);
            *(float2*)(out + lo) = make_float2(av[tm][np][0] * inv0 + x0.x,
                                               av[tm][np][1] * inv0 + x0.y);
            *(float2*)(out + hi) = make_float2(av[tm][np][2] * inv1 + x1.x,
                                               av[tm][np][3] * inv1 + x1.y);
        }
    }
}

// ---------------- launcher ----------------
extern "C" void kernel_launch(void* const* d_in, const int* in_sizes, int n_in,
                              void* d_out, int out_size) {
    const float* x     = (const float*)d_in[0];
    const float* WQ_w  = (const float*)d_in[1];
    const float* WQ_b  = (const float*)d_in[2];
    const float* WK_w  = (const float*)d_in[3];
    const float* WK_b  = (const float*)d_in[4];
    const float* WV_w  = (const float*)d_in[5];
    const float* WV_b  = (const float*)d_in[6];
    const float* gamma = (const float*)d_in[7];
    const float* beta  = (const float*)d_in[8];
    float* out = (float*)d_out;

    cudaFuncSetAttribute(gemm_mma, cudaFuncAttributeMaxDynamicSharedMemorySize,
                         SMEM_GEMM);
    cudaFuncSetAttribute(attn_tc, cudaFuncAttributeMaxDynamicSharedMemorySize,
                         SMEM_ATTN);

    bn_pass1<<<dim3(FEAT / 256, RCHUNKS), 256>>>(x);
    w_fp16<<<384, 256>>>(WQ_w, WK_w, WV_w);
    bn_pass2<<<FEAT / 256, 256>>>(gamma, beta);
    xn_fp16<<<(MROWS * 256 / 8) / 256, 256>>>(x);
    gemm_mma<<<dim3(3, 512), 512, SMEM_GEMM>>>(WQ_b, WK_b, WV_b);
    attn_tc<<<dim3(BATCH, 2), 128, SMEM_ATTN>>>(x, out);
}